// round 6
// baseline (speedup 1.0000x reference)
#include <cuda_runtime.h>
#include <math.h>

#define NPIX   784
#define NPOS   676
#define NCH    8
#define NCLS   10
#define FLATK  5408
#define THREADS 128
#define IMGB   4

// Transposed dense weights: g_wt[cp*3 + j] = {w_{4j}..w_{4j+3}},
// w_o = wdense[o*5408 + cp], rows padded to 12 floats. 260 KB static scratch.
__device__ float4 g_wt[FLATK * 3];

__global__ void prep_wdense(const float* __restrict__ wd)
{
    int idx = blockIdx.x * blockDim.x + threadIdx.x;
    if (idx >= FLATK * 3) return;
    int cp = idx / 3, j = idx - cp * 3;
    float v[4];
    #pragma unroll
    for (int k = 0; k < 4; k++) {
        int o = j * 4 + k;
        v[k] = (o < NCLS) ? wd[o * FLATK + cp] : 0.0f;
    }
    g_wt[idx] = make_float4(v[0], v[1], v[2], v[3]);
}

// Tree max over the 9-pixel window for one image (field F of float4),
// all operands in registers — NO pointer indexing into register arrays.
#define FZ_FIELD(F)                                                        \
    ({                                                                     \
        float a0 = q[0].F + w[0];                                          \
        float a1 = q[1].F + w[1];                                          \
        float a2 = q[2].F + w[2];                                          \
        float a3 = q[3].F + w[3];                                          \
        float a4 = q[4].F + w[4];                                          \
        float a5 = q[5].F + w[5];                                          \
        float a6 = q[6].F + w[6];                                          \
        float a7 = q[7].F + w[7];                                          \
        float a8 = q[8].F + w[8];                                          \
        float b0 = fmaxf(a0, a1);                                          \
        float b1 = fmaxf(a2, a3);                                          \
        float b2 = fmaxf(a4, a5);                                          \
        float b3 = fmaxf(a6, a7);                                          \
        fmaxf(fmaxf(fmaxf(fmaxf(b0, b1), fmaxf(b2, b3)), a8), 0.0f);       \
    })

__global__ __launch_bounds__(THREADS, 4)
void fused_afrnn_kernel(const float* __restrict__ x,
                        const float* __restrict__ wfuzzy,
                        float* __restrict__ out)
{
    __shared__ float4 sx4[NPIX];        // {im0..im3} per pixel, 12.5 KB
    __shared__ float4 swf[NCH * 3];     // (w-1) padded to 12/row
    __shared__ float  red[4][IMGB * NCLS];
    __shared__ float  tot[IMGB * NCLS];

    const int tid  = threadIdx.x;
    const int img0 = blockIdx.x * IMGB;

    // ---- stage: transpose 4 images into interleaved smem ----
    {
        float* sxs = (float*)sx4;
        const float* x0 = x + (size_t)img0 * NPIX;
        for (int idx = tid; idx < IMGB * NPIX; idx += THREADS) {
            int im  = idx / NPIX;
            int pix = idx - im * NPIX;
            sxs[pix * 4 + im] = x0[idx];
        }
        if (tid < NCH * 3) {
            int c = tid / 3, j = tid - c * 3;
            float v[4];
            #pragma unroll
            for (int k = 0; k < 4; k++) {
                int o = j * 4 + k;
                v[k] = (o < 9) ? (wfuzzy[c * 9 + o] - 1.0f) : 0.0f;
            }
            swf[tid] = make_float4(v[0], v[1], v[2], v[3]);
        }
    }
    __syncthreads();

    float acc[IMGB][NCLS];
    #pragma unroll
    for (int im = 0; im < IMGB; im++)
        #pragma unroll
        for (int o = 0; o < NCLS; o++) acc[im][o] = 0.0f;

    for (int p = tid; p < NPOS; p += THREADS) {
        const int i    = p / 26;
        const int j    = p - i * 26;
        const int base = i * 28 + j;

        // 3x3 window x 4 images: 9 LDS.128, conflict-free
        float4 q[9];
        #pragma unroll
        for (int r = 0; r < 3; r++)
            #pragma unroll
            for (int cc = 0; cc < 3; cc++)
                q[r * 3 + cc] = sx4[base + r * 28 + cc];

        #pragma unroll
        for (int c = 0; c < NCH; c++) {
            // fuzzy weights (w-1): 3 broadcast LDS.128
            const float4 wA = swf[c * 3 + 0];
            const float4 wB = swf[c * 3 + 1];
            const float4 wC = swf[c * 3 + 2];
            const float w[9] = { wA.x, wA.y, wA.z, wA.w,
                                 wB.x, wB.y, wB.z, wB.w, wC.x };

            const float fz0 = FZ_FIELD(x);
            const float fz1 = FZ_FIELD(y);
            const float fz2 = FZ_FIELD(z);
            const float fz3 = FZ_FIELD(w);

            // dense: 10 weights via 2x LDG.128 + 1x LDG.64 (transposed rows)
            const char* row = (const char*)(g_wt + ((size_t)c * NPOS + p) * 3);
            const float4 t0 = __ldg((const float4*)row);
            const float4 t1 = __ldg((const float4*)(row + 16));
            const float2 t2 = __ldg((const float2*)(row + 32));
            const float wv[NCLS] = { t0.x, t0.y, t0.z, t0.w,
                                     t1.x, t1.y, t1.z, t1.w,
                                     t2.x, t2.y };
            #pragma unroll
            for (int o = 0; o < NCLS; o++) {
                acc[0][o] = fmaf(fz0, wv[o], acc[0][o]);
                acc[1][o] = fmaf(fz1, wv[o], acc[1][o]);
                acc[2][o] = fmaf(fz2, wv[o], acc[2][o]);
                acc[3][o] = fmaf(fz3, wv[o], acc[3][o]);
            }
        }
    }

    // ---- reduce partial logits across the block ----
    const int lane = tid & 31;
    const int wid  = tid >> 5;
    #pragma unroll
    for (int im = 0; im < IMGB; im++) {
        #pragma unroll
        for (int o = 0; o < NCLS; o++) {
            float t = acc[im][o];
            t += __shfl_down_sync(0xffffffffu, t, 16);
            t += __shfl_down_sync(0xffffffffu, t, 8);
            t += __shfl_down_sync(0xffffffffu, t, 4);
            t += __shfl_down_sync(0xffffffffu, t, 2);
            t += __shfl_down_sync(0xffffffffu, t, 1);
            if (lane == 0) red[wid][im * NCLS + o] = t;
        }
    }
    __syncthreads();

    if (tid < IMGB * NCLS)
        tot[tid] = red[0][tid] + red[1][tid] + red[2][tid] + red[3][tid];
    __syncthreads();

    // ---- log_softmax (1 thread per image) ----
    if (tid < IMGB) {
        float l[NCLS];
        float mx = -1e30f;
        #pragma unroll
        for (int o = 0; o < NCLS; o++) {
            l[o] = tot[tid * NCLS + o];
            mx = fmaxf(mx, l[o]);
        }
        float s = 0.0f;
        #pragma unroll
        for (int o = 0; o < NCLS; o++) s += expf(l[o] - mx);
        const float lse = mx + logf(s);
        float* op = out + (size_t)(img0 + tid) * NCLS;
        #pragma unroll
        for (int o = 0; o < NCLS; o++) op[o] = l[o] - lse;
    }
}

extern "C" void kernel_launch(void* const* d_in, const int* in_sizes, int n_in,
                              void* d_out, int out_size)
{
    const float* x  = (const float*)d_in[0];   // (4096,1,28,28) fp32
    const float* wf = (const float*)d_in[1];   // (8,1,3,3)      fp32
    const float* wd = (const float*)d_in[2];   // (10,5408)      fp32
    float* out = (float*)d_out;                // (4096,10)      fp32

    const int nimg = in_sizes[0] / NPIX;       // 4096
    prep_wdense<<<(FLATK * 3 + 255) / 256, 256>>>(wd);
    fused_afrnn_kernel<<<nimg / IMGB, THREADS>>>(x, wf, out);
}

// round 7
// speedup vs baseline: 1.0564x; 1.0564x over previous
#include <cuda_runtime.h>
#include <math.h>

#define NPIX   784
#define NPOS   676
#define NCH    8
#define NCLS   10
#define FLATK  5408
#define THREADS 128
#define IMGB   4

// Transposed dense weights in THREE parallel arrays so consecutive p
// (= consecutive lanes) are 16B/8B apart -> coalesced vector loads.
//   g_wA[cp] = {w0,w1,w2,w3}, g_wB[cp] = {w4..w7}, g_wC[cp] = {w8,w9},
// where w_o = wdense[o*5408 + cp].  Total 216 KB static scratch.
__device__ float4 g_wA[FLATK];
__device__ float4 g_wB[FLATK];
__device__ float2 g_wC[FLATK];

__global__ void prep_wdense(const float* __restrict__ wd)
{
    int cp = blockIdx.x * blockDim.x + threadIdx.x;
    if (cp >= FLATK) return;
    g_wA[cp] = make_float4(wd[0 * FLATK + cp], wd[1 * FLATK + cp],
                           wd[2 * FLATK + cp], wd[3 * FLATK + cp]);
    g_wB[cp] = make_float4(wd[4 * FLATK + cp], wd[5 * FLATK + cp],
                           wd[6 * FLATK + cp], wd[7 * FLATK + cp]);
    g_wC[cp] = make_float2(wd[8 * FLATK + cp], wd[9 * FLATK + cp]);
}

// Tree max over the 9-pixel window for one image (field F of float4),
// all operands in registers — NO pointer indexing into register arrays.
#define FZ_FIELD(F)                                                        \
    ({                                                                     \
        float a0 = q[0].F + w[0];                                          \
        float a1 = q[1].F + w[1];                                          \
        float a2 = q[2].F + w[2];                                          \
        float a3 = q[3].F + w[3];                                          \
        float a4 = q[4].F + w[4];                                          \
        float a5 = q[5].F + w[5];                                          \
        float a6 = q[6].F + w[6];                                          \
        float a7 = q[7].F + w[7];                                          \
        float a8 = q[8].F + w[8];                                          \
        float b0 = fmaxf(a0, a1);                                          \
        float b1 = fmaxf(a2, a3);                                          \
        float b2 = fmaxf(a4, a5);                                          \
        float b3 = fmaxf(a6, a7);                                          \
        fmaxf(fmaxf(fmaxf(fmaxf(b0, b1), fmaxf(b2, b3)), a8), 0.0f);       \
    })

__global__ __launch_bounds__(THREADS, 4)
void fused_afrnn_kernel(const float* __restrict__ x,
                        const float* __restrict__ wfuzzy,
                        float* __restrict__ out)
{
    __shared__ float4 sx4[NPIX];        // {im0..im3} per pixel, 12.5 KB
    __shared__ float4 swf[NCH * 3];     // (w-1) padded to 12/row
    __shared__ float  red[4][IMGB * NCLS];
    __shared__ float  tot[IMGB * NCLS];

    const int tid  = threadIdx.x;
    const int img0 = blockIdx.x * IMGB;

    // ---- stage: transpose 4 images into interleaved smem ----
    {
        float* sxs = (float*)sx4;
        const float* x0 = x + (size_t)img0 * NPIX;
        for (int idx = tid; idx < IMGB * NPIX; idx += THREADS) {
            int im  = idx / NPIX;
            int pix = idx - im * NPIX;
            sxs[pix * 4 + im] = x0[idx];
        }
        if (tid < NCH * 3) {
            int c = tid / 3, j = tid - c * 3;
            float v[4];
            #pragma unroll
            for (int k = 0; k < 4; k++) {
                int o = j * 4 + k;
                v[k] = (o < 9) ? (wfuzzy[c * 9 + o] - 1.0f) : 0.0f;
            }
            swf[tid] = make_float4(v[0], v[1], v[2], v[3]);
        }
    }
    __syncthreads();

    float acc[IMGB][NCLS];
    #pragma unroll
    for (int im = 0; im < IMGB; im++)
        #pragma unroll
        for (int o = 0; o < NCLS; o++) acc[im][o] = 0.0f;

    for (int p = tid; p < NPOS; p += THREADS) {
        const int i    = p / 26;
        const int j    = p - i * 26;
        const int base = i * 28 + j;

        // 3x3 window x 4 images: 9 LDS.128, conflict-free
        float4 q[9];
        #pragma unroll
        for (int r = 0; r < 3; r++)
            #pragma unroll
            for (int cc = 0; cc < 3; cc++)
                q[r * 3 + cc] = sx4[base + r * 28 + cc];

        #pragma unroll
        for (int c = 0; c < NCH; c++) {
            // fuzzy weights (w-1): 3 broadcast LDS.128
            const float4 wA = swf[c * 3 + 0];
            const float4 wB = swf[c * 3 + 1];
            const float4 wC = swf[c * 3 + 2];
            const float w[9] = { wA.x, wA.y, wA.z, wA.w,
                                 wB.x, wB.y, wB.z, wB.w, wC.x };

            const float fz0 = FZ_FIELD(x);
            const float fz1 = FZ_FIELD(y);
            const float fz2 = FZ_FIELD(z);
            const float fz3 = FZ_FIELD(w);

            // dense: 10 weights via 3 coalesced vector loads (16B lane stride)
            const int cp = c * NPOS + p;
            const float4 t0 = __ldg(&g_wA[cp]);
            const float4 t1 = __ldg(&g_wB[cp]);
            const float2 t2 = __ldg(&g_wC[cp]);
            const float wv[NCLS] = { t0.x, t0.y, t0.z, t0.w,
                                     t1.x, t1.y, t1.z, t1.w,
                                     t2.x, t2.y };
            #pragma unroll
            for (int o = 0; o < NCLS; o++) {
                acc[0][o] = fmaf(fz0, wv[o], acc[0][o]);
                acc[1][o] = fmaf(fz1, wv[o], acc[1][o]);
                acc[2][o] = fmaf(fz2, wv[o], acc[2][o]);
                acc[3][o] = fmaf(fz3, wv[o], acc[3][o]);
            }
        }
    }

    // ---- reduce partial logits across the block ----
    const int lane = tid & 31;
    const int wid  = tid >> 5;
    #pragma unroll
    for (int im = 0; im < IMGB; im++) {
        #pragma unroll
        for (int o = 0; o < NCLS; o++) {
            float t = acc[im][o];
            t += __shfl_down_sync(0xffffffffu, t, 16);
            t += __shfl_down_sync(0xffffffffu, t, 8);
            t += __shfl_down_sync(0xffffffffu, t, 4);
            t += __shfl_down_sync(0xffffffffu, t, 2);
            t += __shfl_down_sync(0xffffffffu, t, 1);
            if (lane == 0) red[wid][im * NCLS + o] = t;
        }
    }
    __syncthreads();

    if (tid < IMGB * NCLS)
        tot[tid] = red[0][tid] + red[1][tid] + red[2][tid] + red[3][tid];
    __syncthreads();

    // ---- log_softmax (1 thread per image) ----
    if (tid < IMGB) {
        float l[NCLS];
        float mx = -1e30f;
        #pragma unroll
        for (int o = 0; o < NCLS; o++) {
            l[o] = tot[tid * NCLS + o];
            mx = fmaxf(mx, l[o]);
        }
        float s = 0.0f;
        #pragma unroll
        for (int o = 0; o < NCLS; o++) s += expf(l[o] - mx);
        const float lse = mx + logf(s);
        float* op = out + (size_t)(img0 + tid) * NCLS;
        #pragma unroll
        for (int o = 0; o < NCLS; o++) op[o] = l[o] - lse;
    }
}

extern "C" void kernel_launch(void* const* d_in, const int* in_sizes, int n_in,
                              void* d_out, int out_size)
{
    const float* x  = (const float*)d_in[0];   // (4096,1,28,28) fp32
    const float* wf = (const float*)d_in[1];   // (8,1,3,3)      fp32
    const float* wd = (const float*)d_in[2];   // (10,5408)      fp32
    float* out = (float*)d_out;                // (4096,10)      fp32

    const int nimg = in_sizes[0] / NPIX;       // 4096
    prep_wdense<<<(FLATK + 255) / 256, 256>>>(wd);
    fused_afrnn_kernel<<<nimg / IMGB, THREADS>>>(x, wf, out);
}